// round 1
// baseline (speedup 1.0000x reference)
#include <cuda_runtime.h>

typedef unsigned long long ull;

// Problem constants (IN=OUT=64 assumed; N, E, R taken from in_sizes).
#define NR_MAX 32
#define E_MAX  2000000
#define TILE_E 96          // edges per GEMM tile (16 thread-cols x 6 edges)
#define ST     102         // At row stride in floats: even (8B align), 102%32=6 -> 2-way max STS conflict

// ---------------- scratch (static device globals: no allocation) -------------
__device__ int g_perm[E_MAX];
__device__ int g_counts[NR_MAX];
__device__ int g_offsets[NR_MAX + 1];
__device__ int g_cursor[NR_MAX];
__device__ int g_tileBase[NR_MAX + 1];

// ---------------- helpers ----------------------------------------------------
__device__ __forceinline__ ull dup2(float x) {
    ull r;
    asm("mov.b64 %0, {%1, %1};" : "=l"(r) : "f"(x));
    return r;
}
__device__ __forceinline__ void fma2(ull& acc, ull a, ull b) {
    asm("fma.rn.f32x2 %0, %1, %2, %0;" : "+l"(acc) : "l"(a), "l"(b));
}
__device__ __forceinline__ void unpack2(ull v, float& lo, float& hi) {
    asm("mov.b64 {%0, %1}, %2;" : "=f"(lo), "=f"(hi) : "l"(v));
}
__device__ __forceinline__ void red4(float* p, float a, float b, float c, float d) {
    asm volatile("red.global.add.v4.f32 [%0], {%1, %2, %3, %4};"
                 :: "l"(p), "f"(a), "f"(b), "f"(c), "f"(d) : "memory");
}

// ---------------- K0: zero output + relation counters ------------------------
__global__ void k_zero(float4* out4, int n4) {
    int i = blockIdx.x * blockDim.x + threadIdx.x;
    if (i < n4) out4[i] = make_float4(0.f, 0.f, 0.f, 0.f);
    if (blockIdx.x == 0 && threadIdx.x < NR_MAX) g_counts[threadIdx.x] = 0;
}

// ---------------- K1: per-relation histogram (SMEM-aggregated) ---------------
__global__ void k_hist(const int* __restrict__ et, int E, int R) {
    __shared__ int h[NR_MAX];
    if (threadIdx.x < NR_MAX) h[threadIdx.x] = 0;
    __syncthreads();
    for (int i = blockIdx.x * blockDim.x + threadIdx.x; i < E;
         i += gridDim.x * blockDim.x)
        atomicAdd(&h[et[i]], 1);
    __syncthreads();
    if (threadIdx.x < R && h[threadIdx.x]) atomicAdd(&g_counts[threadIdx.x], h[threadIdx.x]);
}

// ---------------- K2: tiny serial scan ---------------------------------------
__global__ void k_scan(int R) {
    int acc = 0, tacc = 0;
    for (int r = 0; r < R; r++) {
        g_offsets[r] = acc;
        g_cursor[r]  = acc;
        g_tileBase[r] = tacc;
        int c = g_counts[r];
        acc  += c;
        tacc += (c + TILE_E - 1) / TILE_E;
    }
    g_offsets[R]  = acc;
    g_tileBase[R] = tacc;
}

// ---------------- K3: bucket edge ids by relation (block-aggregated) ---------
#define SC_CH 2048
__global__ void k_scatter(const int* __restrict__ et, int E, int R) {
    __shared__ int h[NR_MAX], base[NR_MAX];
    if (threadIdx.x < NR_MAX) h[threadIdx.x] = 0;
    __syncthreads();
    int b0 = blockIdx.x * SC_CH;
    int myr[8], myrank[8];
#pragma unroll
    for (int j = 0; j < 8; j++) {
        int i = b0 + j * 256 + threadIdx.x;
        myr[j] = -1;
        if (i < E) {
            myr[j]    = et[i];
            myrank[j] = atomicAdd(&h[myr[j]], 1);
        }
    }
    __syncthreads();
    if (threadIdx.x < R && h[threadIdx.x] > 0)
        base[threadIdx.x] = atomicAdd(&g_cursor[threadIdx.x], h[threadIdx.x]);
    __syncthreads();
#pragma unroll
    for (int j = 0; j < 8; j++) {
        int i = b0 + j * 256 + threadIdx.x;
        if (i < E) g_perm[base[myr[j]] + myrank[j]] = i;
    }
}

// ---------------- K4: grouped GEMM tile + vector-red scatter ------------------
// One block = one relation-tile: C[TILE_E x 64] = A[TILE_E x 64] * W_r[64 x 64]
// Thread layout: tx = tid&15 -> 4 output cols (tx*4..); ty = tid>>4 -> 6 edges (ty*6..)
// Edge pairs packed into f32x2 FMAs; epilogue red.global.add.v4.f32 into out[dst].
__global__ __launch_bounds__(256) void k_main(
    const float* __restrict__ feat, const float* __restrict__ weight,
    const int* __restrict__ src, const int* __restrict__ dst,
    float* __restrict__ out, int R)
{
    __shared__ float At[64 * ST];      // transposed feat tile: At[f][e]
    __shared__ float Ws[64 * 64];      // W_r, row-major [f][o]
    __shared__ int   dsts[TILE_E];

    int t = blockIdx.x;
    if (t >= g_tileBase[R]) return;

    int r = 0;
    for (int i = 1; i < R; i++)
        if (t >= g_tileBase[i]) r = i;
    int start = g_offsets[r] + (t - g_tileBase[r]) * TILE_E;
    int len   = min(TILE_E, g_offsets[r + 1] - start);

    int tid = threadIdx.x;

    // Load W_r (16 KB) -> SMEM
    {
        const float4* wg = (const float4*)(weight + (size_t)r * 4096);
        float4* ws4 = (float4*)Ws;
#pragma unroll
        for (int i = 0; i < 4; i++) ws4[tid + i * 256] = wg[tid + i * 256];
    }

    // Gather feature tile (transposed). 64 threads per edge row -> coalesced 256B reads.
    int f  = tid & 63;
    int e0 = tid >> 6;                 // 0..3
#pragma unroll 4
    for (int p = 0; p < TILE_E / 4; p++) {
        int e = e0 + p * 4;
        float v = 0.f;
        if (e < len) {
            int idx = g_perm[start + e];
            v = feat[(size_t)src[idx] * 64 + f];
            if (f == 0) dsts[e] = dst[idx];
        }
        At[f * ST + e] = v;
    }
    __syncthreads();

    int tx = tid & 15, ty = tid >> 4;
    ull acc[3][4];
#pragma unroll
    for (int j = 0; j < 3; j++)
#pragma unroll
        for (int o = 0; o < 4; o++) acc[j][o] = 0ull;

    const float* arow0 = At + ty * 6;
    const float* brow0 = Ws + tx * 4;

#pragma unroll 8
    for (int k = 0; k < 64; k++) {
        // 3 edge-pairs (broadcast LDS.64 within warp)
        ull a0 = *(const ull*)(arow0 + k * ST + 0);
        ull a1 = *(const ull*)(arow0 + k * ST + 2);
        ull a2 = *(const ull*)(arow0 + k * ST + 4);
        // 4 weights for this k-row (LDS.128)
        float4 b = *(const float4*)(brow0 + k * 64);
        ull b0 = dup2(b.x), b1 = dup2(b.y), b2 = dup2(b.z), b3 = dup2(b.w);
        fma2(acc[0][0], a0, b0); fma2(acc[0][1], a0, b1);
        fma2(acc[0][2], a0, b2); fma2(acc[0][3], a0, b3);
        fma2(acc[1][0], a1, b0); fma2(acc[1][1], a1, b1);
        fma2(acc[1][2], a1, b2); fma2(acc[1][3], a1, b3);
        fma2(acc[2][0], a2, b0); fma2(acc[2][1], a2, b1);
        fma2(acc[2][2], a2, b2); fma2(acc[2][3], a2, b3);
    }

    // Epilogue: 16-byte vector reductions into out[dst]
#pragma unroll
    for (int j = 0; j < 3; j++) {
        float lo[4], hi[4];
#pragma unroll
        for (int o = 0; o < 4; o++) unpack2(acc[j][o], lo[o], hi[o]);
        int e = ty * 6 + 2 * j;
        if (e < len) {
            float* p = out + (size_t)dsts[e] * 64 + tx * 4;
            red4(p, lo[0], lo[1], lo[2], lo[3]);
        }
        if (e + 1 < len) {
            float* p = out + (size_t)dsts[e + 1] * 64 + tx * 4;
            red4(p, hi[0], hi[1], hi[2], hi[3]);
        }
    }
}

// ---------------- launch ------------------------------------------------------
extern "C" void kernel_launch(void* const* d_in, const int* in_sizes, int n_in,
                              void* d_out, int out_size) {
    const float* feat   = (const float*)d_in[0];
    const float* weight = (const float*)d_in[1];
    const int*   src    = (const int*)d_in[2];
    const int*   dst    = (const int*)d_in[3];
    const int*   et     = (const int*)d_in[4];
    float*       out    = (float*)d_out;

    int E = in_sizes[2];
    int R = in_sizes[1] / (64 * 64);
    if (R < 1) R = 1;
    if (R > NR_MAX) R = NR_MAX;

    int n4 = out_size / 4;
    k_zero<<<(n4 + 255) / 256, 256>>>((float4*)d_out, n4);
    k_hist<<<296, 256>>>(et, E, R);
    k_scan<<<1, 1>>>(R);
    k_scatter<<<(E + SC_CH - 1) / SC_CH, 256>>>(et, E, R);

    int maxTiles = (E + TILE_E - 1) / TILE_E + R;
    k_main<<<maxTiles, 256>>>(feat, weight, src, dst, out, R);
}

// round 3
// speedup vs baseline: 1.3942x; 1.3942x over previous
#include <cuda_runtime.h>
#include <cuda_bf16.h>
#include <cstdint>

typedef unsigned long long ull;

#define NR_MAX 32
#define E_MAX  2000000
#define TILE_E 128            // edges per MMA tile (M=128)
#define SA 144                // SMEM row pitch bytes (9*16B: conflict-free STS + ldmatrix)

// ---------------- scratch (static device globals) ----------------------------
__device__ int g_perm[E_MAX];
__device__ int g_counts[NR_MAX];
__device__ int g_offsets[NR_MAX + 1];
__device__ int g_cursor[NR_MAX];
__device__ int g_tileBase[NR_MAX + 1];
// pre-split, pre-transposed weights: per relation [o][f] 64x64 bf16 = 8KB each
__device__ __align__(16) __nv_bfloat16 g_whi[NR_MAX * 64 * 64];
__device__ __align__(16) __nv_bfloat16 g_wlo[NR_MAX * 64 * 64];

// ---------------- ptx helpers -------------------------------------------------
__device__ __forceinline__ uint32_t smem_u32(const void* p) {
    uint32_t a;
    asm("{ .reg .u64 t; cvta.to.shared.u64 t, %1; cvt.u32.u64 %0, t; }" : "=r"(a) : "l"(p));
    return a;
}
__device__ __forceinline__ void ldsm4(uint32_t& r0, uint32_t& r1, uint32_t& r2, uint32_t& r3, uint32_t a) {
    asm volatile("ldmatrix.sync.aligned.m8n8.x4.shared.b16 {%0,%1,%2,%3}, [%4];"
                 : "=r"(r0), "=r"(r1), "=r"(r2), "=r"(r3) : "r"(a));
}
__device__ __forceinline__ void ldsm2(uint32_t& r0, uint32_t& r1, uint32_t a) {
    asm volatile("ldmatrix.sync.aligned.m8n8.x2.shared.b16 {%0,%1}, [%2];"
                 : "=r"(r0), "=r"(r1) : "r"(a));
}
__device__ __forceinline__ void mma_bf16(float* d, uint32_t a0, uint32_t a1, uint32_t a2, uint32_t a3,
                                         uint32_t b0, uint32_t b1) {
    asm volatile(
        "mma.sync.aligned.m16n8k16.row.col.f32.bf16.bf16.f32 "
        "{%0,%1,%2,%3}, {%4,%5,%6,%7}, {%8,%9}, {%0,%1,%2,%3};"
        : "+f"(d[0]), "+f"(d[1]), "+f"(d[2]), "+f"(d[3])
        : "r"(a0), "r"(a1), "r"(a2), "r"(a3), "r"(b0), "r"(b1));
}
__device__ __forceinline__ void red4(float* p, float a, float b, float c, float d) {
    asm volatile("red.global.add.v4.f32 [%0], {%1,%2,%3,%4};"
                 :: "l"(p), "f"(a), "f"(b), "f"(c), "f"(d) : "memory");
}

// ---------------- K0: zero output + counters ----------------------------------
__global__ void k_zero(float4* out4, int n4) {
    int i = blockIdx.x * blockDim.x + threadIdx.x;
    if (i < n4) out4[i] = make_float4(0.f, 0.f, 0.f, 0.f);
    if (blockIdx.x == 0 && threadIdx.x < NR_MAX) g_counts[threadIdx.x] = 0;
}

// ---------------- K0b: split + transpose weights ------------------------------
__global__ void k_wprep(const float* __restrict__ weight, int R) {
    int i = blockIdx.x * blockDim.x + threadIdx.x;   // over R*4096
    if (i >= R * 4096) return;
    int r = i >> 12, f = (i >> 6) & 63, o = i & 63;
    float w = weight[i];
    __nv_bfloat16 h = __float2bfloat16(w);
    __nv_bfloat16 l = __float2bfloat16(w - __bfloat162float(h));
    g_whi[r * 4096 + o * 64 + f] = h;     // B stored [o][f], f contiguous (col-major B)
    g_wlo[r * 4096 + o * 64 + f] = l;
}

// ---------------- K1: per-relation histogram ----------------------------------
__global__ void k_hist(const int* __restrict__ et, int E, int R) {
    __shared__ int h[NR_MAX];
    if (threadIdx.x < NR_MAX) h[threadIdx.x] = 0;
    __syncthreads();
    for (int i = blockIdx.x * blockDim.x + threadIdx.x; i < E; i += gridDim.x * blockDim.x)
        atomicAdd(&h[et[i]], 1);
    __syncthreads();
    if (threadIdx.x < R && h[threadIdx.x]) atomicAdd(&g_counts[threadIdx.x], h[threadIdx.x]);
}

// ---------------- K2: tiny scan -----------------------------------------------
__global__ void k_scan(int R) {
    int acc = 0, tacc = 0;
    for (int r = 0; r < R; r++) {
        g_offsets[r] = acc; g_cursor[r] = acc; g_tileBase[r] = tacc;
        int c = g_counts[r];
        acc += c; tacc += (c + TILE_E - 1) / TILE_E;
    }
    g_offsets[R] = acc; g_tileBase[R] = tacc;
}

// ---------------- K3: bucket edge ids -----------------------------------------
#define SC_CH 2048
__global__ void k_scatter(const int* __restrict__ et, int E, int R) {
    __shared__ int h[NR_MAX], base[NR_MAX];
    if (threadIdx.x < NR_MAX) h[threadIdx.x] = 0;
    __syncthreads();
    int b0 = blockIdx.x * SC_CH;
    int myr[8], myrank[8];
#pragma unroll
    for (int j = 0; j < 8; j++) {
        int i = b0 + j * 256 + threadIdx.x;
        myr[j] = -1;
        if (i < E) { myr[j] = et[i]; myrank[j] = atomicAdd(&h[myr[j]], 1); }
    }
    __syncthreads();
    if (threadIdx.x < R && h[threadIdx.x] > 0)
        base[threadIdx.x] = atomicAdd(&g_cursor[threadIdx.x], h[threadIdx.x]);
    __syncthreads();
#pragma unroll
    for (int j = 0; j < 8; j++) {
        int i = b0 + j * 256 + threadIdx.x;
        if (i < E) g_perm[base[myr[j]] + myrank[j]] = i;
    }
}

// ---------------- K4: HMMA grouped-GEMM tile ----------------------------------
// SMEM byte offsets
#define OFF_DST  0
#define OFF_SRC  512
#define OFF_AHI  1024                      // 128 x SA
#define OFF_ALO  (OFF_AHI + 128 * SA)      // 19456
#define OFF_BHI  (OFF_ALO + 128 * SA)      // 37888: 64 x SA
#define OFF_BLO  (OFF_BHI + 64 * SA)       // 47104
#define SMEM_SZ  (OFF_BLO + 64 * SA)       // 56320

__global__ __launch_bounds__(256, 3) void k_main(
    const float* __restrict__ feat,
    const int* __restrict__ src, const int* __restrict__ dst,
    float* __restrict__ out, int R)
{
    extern __shared__ char smem[];
    uint32_t sb = smem_u32(smem);
    int tid = threadIdx.x;
    int wid = tid >> 5, lid = tid & 31;

    int t = blockIdx.x;
    if (t >= g_tileBase[R]) return;

    // relation + edge range for this tile
    int r = 0;
#pragma unroll 1
    for (int i = 1; i < NR_MAX; i++)
        if (i < R && t >= g_tileBase[i]) r = i;
    int start = g_offsets[r] + (t - g_tileBase[r]) * TILE_E;
    int len = min(TILE_E, g_offsets[r + 1] - start);

    int* dsts = (int*)(smem + OFF_DST);
    int* ssrc = (int*)(smem + OFF_SRC);

    // Phase A: resolve src/dst for this tile's edges
    if (tid < TILE_E) {
        int s = -1;
        if (tid < len) {
            int idx = g_perm[start + tid];
            s = src[idx];
            dsts[tid] = dst[idx];
        }
        ssrc[tid] = s;
    }

    // Load B hi/lo (8KB each) into SMEM with SA pitch: 512 16B-chunks each
    {
        const char* wh = (const char*)g_whi + (size_t)r * 8192;
        const char* wl = (const char*)g_wlo + (size_t)r * 8192;
#pragma unroll
        for (int j = 0; j < 2; j++) {
            int c = j * 256 + tid;            // 0..511
            int row = c >> 3, col = c & 7;    // row 0..63, 16B chunk 0..7
            uint4 vh = *(const uint4*)(wh + row * 128 + col * 16);
            uint4 vl = *(const uint4*)(wl + row * 128 + col * 16);
            *(uint4*)(smem + OFF_BHI + row * SA + col * 16) = vh;
            *(uint4*)(smem + OFF_BLO + row * SA + col * 16) = vl;
        }
    }
    __syncthreads();

    // Phase B: gather feature rows, split to bf16 hi/lo, STS at SA pitch
#pragma unroll
    for (int it = 0; it < 8; it++) {
        int i = it * 256 + tid;         // 0..2047
        int e = i >> 4, c = i & 15;     // edge, float4-chunk
        int s = ssrc[e];
        float4 v = make_float4(0.f, 0.f, 0.f, 0.f);
        if (s >= 0) v = ((const float4*)feat)[(size_t)s * 16 + c];
        __nv_bfloat16 hx = __float2bfloat16(v.x), hy = __float2bfloat16(v.y);
        __nv_bfloat16 hz = __float2bfloat16(v.z), hw = __float2bfloat16(v.w);
        uint2 hp, lp;
        hp.x = (uint32_t)__bfloat16_as_ushort(hx) | ((uint32_t)__bfloat16_as_ushort(hy) << 16);
        hp.y = (uint32_t)__bfloat16_as_ushort(hz) | ((uint32_t)__bfloat16_as_ushort(hw) << 16);
        __nv_bfloat16 lx = __float2bfloat16(v.x - __bfloat162float(hx));
        __nv_bfloat16 ly = __float2bfloat16(v.y - __bfloat162float(hy));
        __nv_bfloat16 lz = __float2bfloat16(v.z - __bfloat162float(hz));
        __nv_bfloat16 lw = __float2bfloat16(v.w - __bfloat162float(hw));
        lp.x = (uint32_t)__bfloat16_as_ushort(lx) | ((uint32_t)__bfloat16_as_ushort(ly) << 16);
        lp.y = (uint32_t)__bfloat16_as_ushort(lz) | ((uint32_t)__bfloat16_as_ushort(lw) << 16);
        *(uint2*)(smem + OFF_AHI + e * SA + c * 8) = hp;
        *(uint2*)(smem + OFF_ALO + e * SA + c * 8) = lp;
    }
    __syncthreads();

    // MMA: D = aH*bH + aH*bL + aL*bH, fp32 accum in registers.
    // Warp w handles rows [w*16, w*16+16); 8 n-tiles of 8 cols; 4 k-steps of 16.
    float acc[8][4];
#pragma unroll
    for (int i = 0; i < 8; i++)
#pragma unroll
        for (int j = 0; j < 4; j++) acc[i][j] = 0.f;

    int wr = wid * 16;
    // ldmatrix lane addressing
    uint32_t a_off = (uint32_t)(wr + (lid & 15)) * SA + (uint32_t)((lid >> 4) << 4);  // (lane>>4)*8 cols *2B
    uint32_t b_off = (uint32_t)(lid & 7) * SA + (uint32_t)(((lid >> 3) & 1) << 4);

#pragma unroll
    for (int kk = 0; kk < 4; kk++) {
        uint32_t ka = a_off + kk * 32;      // k0 = kk*16 -> *2 bytes
        uint32_t aH0, aH1, aH2, aH3, aL0, aL1, aL2, aL3;
        ldsm4(aH0, aH1, aH2, aH3, sb + OFF_AHI + ka);
        ldsm4(aL0, aL1, aL2, aL3, sb + OFF_ALO + ka);
#pragma unroll
        for (int nt = 0; nt < 8; nt++) {
            uint32_t kb = b_off + nt * 8 * SA + kk * 32;
            uint32_t bH0, bH1, bL0, bL1;
            ldsm2(bH0, bH1, sb + OFF_BHI + kb);
            ldsm2(bL0, bL1, sb + OFF_BLO + kb);
            mma_bf16(acc[nt], aH0, aH1, aH2, aH3, bH0, bH1);
            mma_bf16(acc[nt], aH0, aH1, aH2, aH3, bL0, bL1);
            mma_bf16(acc[nt], aL0, aL1, aL2, aL3, bH0, bH1);
        }
    }

    // Epilogue: repack D fragments to 16B via shfl.xor(1), red.global.add.v4
    int g = lid >> 2, tig = lid & 3;
    bool even = (tig & 1) == 0;
    int row = even ? (wr + g) : (wr + g + 8);
    int cb = even ? (tig * 2) : ((tig - 1) * 2);
    bool live = row < len;
    float* pbase = live ? (out + (size_t)dsts[row] * 64 + cb) : out;
#pragma unroll
    for (int nt = 0; nt < 8; nt++) {
        float o0 = __shfl_xor_sync(0xffffffffu, acc[nt][0], 1);
        float o1 = __shfl_xor_sync(0xffffffffu, acc[nt][1], 1);
        float o2 = __shfl_xor_sync(0xffffffffu, acc[nt][2], 1);
        float o3 = __shfl_xor_sync(0xffffffffu, acc[nt][3], 1);
        if (live) {
            if (even) red4(pbase + nt * 8, acc[nt][0], acc[nt][1], o0, o1);
            else      red4(pbase + nt * 8, o2, o3, acc[nt][2], acc[nt][3]);
        }
    }
}

// ---------------- launch ------------------------------------------------------
extern "C" void kernel_launch(void* const* d_in, const int* in_sizes, int n_in,
                              void* d_out, int out_size) {
    const float* feat   = (const float*)d_in[0];
    const float* weight = (const float*)d_in[1];
    const int*   src    = (const int*)d_in[2];
    const int*   dst    = (const int*)d_in[3];
    const int*   et     = (const int*)d_in[4];
    float*       out    = (float*)d_out;

    int E = in_sizes[2];
    int R = in_sizes[1] / 4096;
    if (R < 1) R = 1;
    if (R > NR_MAX) R = NR_MAX;

    cudaFuncSetAttribute(k_main, cudaFuncAttributeMaxDynamicSharedMemorySize, SMEM_SZ);

    int n4 = out_size / 4;
    k_zero<<<(n4 + 255) / 256, 256>>>((float4*)d_out, n4);
    k_wprep<<<(R * 4096 + 255) / 256, 256>>>(weight, R);
    k_hist<<<296, 256>>>(et, E, R);
    k_scan<<<1, 1>>>(R);
    k_scatter<<<(E + SC_CH - 1) / SC_CH, 256>>>(et, E, R);

    int maxTiles = (E + TILE_E - 1) / TILE_E + R;
    k_main<<<maxTiles, 256, SMEM_SZ>>>(feat, src, dst, out, R);
}

// round 4
// speedup vs baseline: 1.4699x; 1.0543x over previous
#include <cuda_runtime.h>
#include <cuda_bf16.h>
#include <cstdint>

typedef unsigned long long ull;

#define NR_MAX 32
#define E_MAX  2000000
#define N_MAX  200000
#define TILE_E 256            // edges per MMA tile (M=256)
#define SA 144                // SMEM row pitch bytes (9*16B)

// ---------------- scratch (static device globals) ----------------------------
__device__ int g_perm[E_MAX];
__device__ int g_counts[NR_MAX];          // zero-init; k_scan re-zeros after use
__device__ int g_offsets[NR_MAX + 1];
__device__ int g_cursor[NR_MAX];
__device__ int g_tileBase[NR_MAX + 1];
// pre-split weights [r][o][f] bf16 (8KB/rel each)
__device__ __align__(16) __nv_bfloat16 g_whi[NR_MAX * 64 * 64];
__device__ __align__(16) __nv_bfloat16 g_wlo[NR_MAX * 64 * 64];
// pre-split features [n][f] bf16 (128B rows)
__device__ __align__(16) __nv_bfloat16 g_fhi[N_MAX * 64];
__device__ __align__(16) __nv_bfloat16 g_flo[N_MAX * 64];

// ---------------- ptx helpers -------------------------------------------------
__device__ __forceinline__ uint32_t smem_u32(const void* p) {
    uint32_t a;
    asm("{ .reg .u64 t; cvta.to.shared.u64 t, %1; cvt.u32.u64 %0, t; }" : "=r"(a) : "l"(p));
    return a;
}
__device__ __forceinline__ void cpa16(uint32_t dst, const void* src, int sz) {
    asm volatile("cp.async.cg.shared.global [%0], [%1], 16, %2;"
                 :: "r"(dst), "l"(src), "r"(sz) : "memory");
}
__device__ __forceinline__ void cpa_commit_wait() {
    asm volatile("cp.async.commit_group;" ::: "memory");
    asm volatile("cp.async.wait_group 0;" ::: "memory");
}
__device__ __forceinline__ void ldsm4(uint32_t& r0, uint32_t& r1, uint32_t& r2, uint32_t& r3, uint32_t a) {
    asm volatile("ldmatrix.sync.aligned.m8n8.x4.shared.b16 {%0,%1,%2,%3}, [%4];"
                 : "=r"(r0), "=r"(r1), "=r"(r2), "=r"(r3) : "r"(a));
}
__device__ __forceinline__ void mma_bf16(float* d, uint32_t a0, uint32_t a1, uint32_t a2, uint32_t a3,
                                         uint32_t b0, uint32_t b1) {
    asm volatile(
        "mma.sync.aligned.m16n8k16.row.col.f32.bf16.bf16.f32 "
        "{%0,%1,%2,%3}, {%4,%5,%6,%7}, {%8,%9}, {%0,%1,%2,%3};"
        : "+f"(d[0]), "+f"(d[1]), "+f"(d[2]), "+f"(d[3])
        : "r"(a0), "r"(a1), "r"(a2), "r"(a3), "r"(b0), "r"(b1));
}
__device__ __forceinline__ void red4(float* p, float a, float b, float c, float d) {
    asm volatile("red.global.add.v4.f32 [%0], {%1,%2,%3,%4};"
                 :: "l"(p), "f"(a), "f"(b), "f"(c), "f"(d) : "memory");
}

// ---------------- K1: fused prep (zero out, split W, split feat, histogram) ---
__global__ void k_prep(float4* out4, int n4,
                       const float* __restrict__ feat, int NF,   // N*64
                       const float* __restrict__ weight, int RW, // R*4096
                       const int* __restrict__ et, int E) {
    int gtid = blockIdx.x * blockDim.x + threadIdx.x;
    int gsz  = gridDim.x * blockDim.x;

    // zero output
    for (int i = gtid; i < n4; i += gsz) out4[i] = make_float4(0.f, 0.f, 0.f, 0.f);

    // split + transpose weights: [r][f][o] fp32 -> [r][o][f] bf16 hi/lo
    for (int i = gtid; i < RW; i += gsz) {
        int r = i >> 12, f = (i >> 6) & 63, o = i & 63;
        float w = weight[i];
        __nv_bfloat16 h = __float2bfloat16(w);
        __nv_bfloat16 l = __float2bfloat16(w - __bfloat162float(h));
        g_whi[r * 4096 + o * 64 + f] = h;
        g_wlo[r * 4096 + o * 64 + f] = l;
    }

    // split features
    for (int i = gtid; i < NF; i += gsz) {
        float v = feat[i];
        __nv_bfloat16 h = __float2bfloat16(v);
        g_fhi[i] = h;
        g_flo[i] = __float2bfloat16(v - __bfloat162float(h));
    }

    // histogram (smem-aggregated); g_counts is 0 on entry (init or k_scan reset)
    __shared__ int h[NR_MAX];
    if (threadIdx.x < NR_MAX) h[threadIdx.x] = 0;
    __syncthreads();
    for (int i = gtid; i < E; i += gsz) atomicAdd(&h[et[i]], 1);
    __syncthreads();
    if (threadIdx.x < NR_MAX && h[threadIdx.x]) atomicAdd(&g_counts[threadIdx.x], h[threadIdx.x]);
}

// ---------------- K2: tiny scan (re-zeros g_counts for graph replay) ----------
__global__ void k_scan(int R) {
    int acc = 0, tacc = 0;
    for (int r = 0; r < R; r++) {
        g_offsets[r] = acc; g_cursor[r] = acc; g_tileBase[r] = tacc;
        int c = g_counts[r];
        g_counts[r] = 0;                    // reset for next replay
        acc += c; tacc += (c + TILE_E - 1) / TILE_E;
    }
    g_offsets[R] = acc; g_tileBase[R] = tacc;
}

// ---------------- K3: bucket edge ids -----------------------------------------
#define SC_CH 2048
__global__ void k_scatter(const int* __restrict__ et, int E, int R) {
    __shared__ int h[NR_MAX], base[NR_MAX];
    if (threadIdx.x < NR_MAX) h[threadIdx.x] = 0;
    __syncthreads();
    int b0 = blockIdx.x * SC_CH;
    int myr[8], myrank[8];
#pragma unroll
    for (int j = 0; j < 8; j++) {
        int i = b0 + j * 256 + threadIdx.x;
        myr[j] = -1;
        if (i < E) { myr[j] = et[i]; myrank[j] = atomicAdd(&h[myr[j]], 1); }
    }
    __syncthreads();
    if (threadIdx.x < R && h[threadIdx.x] > 0)
        base[threadIdx.x] = atomicAdd(&g_cursor[threadIdx.x], h[threadIdx.x]);
    __syncthreads();
#pragma unroll
    for (int j = 0; j < 8; j++) {
        int i = b0 + j * 256 + threadIdx.x;
        if (i < E) g_perm[base[myr[j]] + myrank[j]] = i;
    }
}

// ---------------- K4: HMMA grouped-GEMM tile (M=256) --------------------------
#define OFF_DST  0                          // int[256]
#define OFF_AHI  1024                       // 256 x SA = 36864
#define OFF_ALO  (OFF_AHI + 256 * SA)       // 37888
#define OFF_BHI  (OFF_ALO + 256 * SA)       // 74752: 64 x SA
#define OFF_BLO  (OFF_BHI + 64 * SA)        // 83968
#define SMEM_SZ  (OFF_BLO + 64 * SA)        // 93184

__global__ __launch_bounds__(256, 2) void k_main(
    const int* __restrict__ src, const int* __restrict__ dst,
    float* __restrict__ out, int R)
{
    extern __shared__ char smem[];
    uint32_t sb = smem_u32(smem);
    int tid = threadIdx.x;
    int wid = tid >> 5, lid = tid & 31;

    int t = blockIdx.x;
    if (t >= g_tileBase[R]) return;

    // relation + edge range
    int r = 0;
#pragma unroll 1
    for (int i = 1; i < NR_MAX; i++)
        if (i < R && t >= g_tileBase[i]) r = i;
    int start = g_offsets[r] + (t - g_tileBase[r]) * TILE_E;
    int len = min(TILE_E, g_offsets[r + 1] - start);

    int* dsts = (int*)(smem + OFF_DST);

    // Phase A: per-thread edge resolve + cp.async gather of hi/lo rows
    {
        int e = tid, s = -1;
        if (e < len) {
            int idx = g_perm[start + e];
            s = src[idx];
            dsts[e] = dst[idx];
        }
        size_t ro = (size_t)(s >= 0 ? s : 0) * 128;
        const char* hs = (const char*)g_fhi + ro;
        const char* ls = (const char*)g_flo + ro;
        int sz = (s >= 0) ? 16 : 0;
        uint32_t da = sb + OFF_AHI + e * SA;
        uint32_t dl = sb + OFF_ALO + e * SA;
#pragma unroll
        for (int c = 0; c < 8; c++) {
            cpa16(da + c * 16, hs + c * 16, sz);
            cpa16(dl + c * 16, ls + c * 16, sz);
        }
    }
    // B tiles via cp.async: 1024 16B lanes (hi 512 + lo 512)
    {
        const char* wh = (const char*)g_whi + (size_t)r * 8192;
        const char* wl = (const char*)g_wlo + (size_t)r * 8192;
#pragma unroll
        for (int j = 0; j < 2; j++) {
            int c = j * 256 + tid;            // 0..511
            int row = c >> 3, col = c & 7;
            cpa16(sb + OFF_BHI + row * SA + col * 16, wh + row * 128 + col * 16, 16);
            cpa16(sb + OFF_BLO + row * SA + col * 16, wl + row * 128 + col * 16, 16);
        }
    }
    cpa_commit_wait();
    __syncthreads();

    // MMA: D = aH*bH + aH*bL + aL*bH; warp handles 32 rows (2 m16 row-tiles)
    float acc[2][8][4];
#pragma unroll
    for (int rt = 0; rt < 2; rt++)
#pragma unroll
        for (int i = 0; i < 8; i++)
#pragma unroll
            for (int j = 0; j < 4; j++) acc[rt][i][j] = 0.f;

    int wr = wid * 32;
    uint32_t a_lane = (uint32_t)(lid & 15) * SA + ((uint32_t)(lid >> 4) << 4);
    uint32_t b_lane = (uint32_t)(lid & 7) * SA + (uint32_t)((lid >> 3) & 1) * 16
                    + (uint32_t)(lid >> 4) * 8 * SA;

#pragma unroll
    for (int kk = 0; kk < 4; kk++) {
        uint32_t ka = kk * 32;
        uint32_t aH[2][4], aL[2][4];
#pragma unroll
        for (int rt = 0; rt < 2; rt++) {
            uint32_t arow = (uint32_t)(wr + rt * 16) * SA + a_lane + ka;
            ldsm4(aH[rt][0], aH[rt][1], aH[rt][2], aH[rt][3], sb + OFF_AHI + arow);
            ldsm4(aL[rt][0], aL[rt][1], aL[rt][2], aL[rt][3], sb + OFF_ALO + arow);
        }
#pragma unroll
        for (int p = 0; p < 4; p++) {
            uint32_t brow = (uint32_t)p * 16 * SA + b_lane + ka;
            uint32_t bh0, bh1, bh2, bh3, bl0, bl1, bl2, bl3;
            ldsm4(bh0, bh1, bh2, bh3, sb + OFF_BHI + brow);
            ldsm4(bl0, bl1, bl2, bl3, sb + OFF_BLO + brow);
#pragma unroll
            for (int rt = 0; rt < 2; rt++) {
                mma_bf16(acc[rt][2 * p],     aH[rt][0], aH[rt][1], aH[rt][2], aH[rt][3], bh0, bh1);
                mma_bf16(acc[rt][2 * p],     aH[rt][0], aH[rt][1], aH[rt][2], aH[rt][3], bl0, bl1);
                mma_bf16(acc[rt][2 * p],     aL[rt][0], aL[rt][1], aL[rt][2], aL[rt][3], bh0, bh1);
                mma_bf16(acc[rt][2 * p + 1], aH[rt][0], aH[rt][1], aH[rt][2], aH[rt][3], bh2, bh3);
                mma_bf16(acc[rt][2 * p + 1], aH[rt][0], aH[rt][1], aH[rt][2], aH[rt][3], bl2, bl3);
                mma_bf16(acc[rt][2 * p + 1], aL[rt][0], aL[rt][1], aL[rt][2], aL[rt][3], bh2, bh3);
            }
        }
    }

    // Epilogue: repack to 16B via shfl.xor(1), red.global.add.v4
    int g = lid >> 2, tig = lid & 3;
    bool even = (tig & 1) == 0;
    int cb = even ? (tig * 2) : ((tig - 1) * 2);
#pragma unroll
    for (int rt = 0; rt < 2; rt++) {
        int row = wr + rt * 16 + g + (even ? 0 : 8);
        bool live = row < len;
        float* pbase = live ? (out + (size_t)dsts[row] * 64 + cb) : out;
#pragma unroll
        for (int nt = 0; nt < 8; nt++) {
            float o0 = __shfl_xor_sync(0xffffffffu, acc[rt][nt][0], 1);
            float o1 = __shfl_xor_sync(0xffffffffu, acc[rt][nt][1], 1);
            float o2 = __shfl_xor_sync(0xffffffffu, acc[rt][nt][2], 1);
            float o3 = __shfl_xor_sync(0xffffffffu, acc[rt][nt][3], 1);
            if (live) {
                if (even) red4(pbase + nt * 8, acc[rt][nt][0], acc[rt][nt][1], o0, o1);
                else      red4(pbase + nt * 8, o2, o3, acc[rt][nt][2], acc[rt][nt][3]);
            }
        }
    }
}

// ---------------- launch ------------------------------------------------------
extern "C" void kernel_launch(void* const* d_in, const int* in_sizes, int n_in,
                              void* d_out, int out_size) {
    const float* feat   = (const float*)d_in[0];
    const float* weight = (const float*)d_in[1];
    const int*   src    = (const int*)d_in[2];
    const int*   dst    = (const int*)d_in[3];
    const int*   et     = (const int*)d_in[4];
    float*       out    = (float*)d_out;

    int NF = in_sizes[0];            // N*64
    int RW = in_sizes[1];            // R*4096
    int E  = in_sizes[2];
    int R  = RW / 4096;
    if (R < 1) R = 1;
    if (R > NR_MAX) R = NR_MAX;

    cudaFuncSetAttribute(k_main, cudaFuncAttributeMaxDynamicSharedMemorySize, SMEM_SZ);

    int n4 = out_size / 4;
    k_prep<<<1184, 256>>>((float4*)d_out, n4, feat, NF, weight, RW, et, E);
    k_scan<<<1, 1>>>(R);
    k_scatter<<<(E + SC_CH - 1) / SC_CH, 256>>>(et, E, R);

    int maxTiles = (E + TILE_E - 1) / TILE_E + R;
    k_main<<<maxTiles, 256, SMEM_SZ>>>(src, dst, out, R);
}